// round 9
// baseline (speedup 1.0000x reference)
#include <cuda_runtime.h>

// Problem constants
#define Bsz    64
#define Lseq   2048
#define Dm     512
#define NC1    8               // chunks for mean pass (R5-proven)
#define TOK1   (Lseq / NC1)    // 256 tokens per chunk
#define QSPLIT 4               // token-parallel groups inside a k_hpart block
#define NC2    16              // chunks for attention pass
#define TOK2   (Lseq / NC2)    // 128 tokens per chunk
#define WARPS_C 8              // warps per block in kernel C
#define TOKW   (TOK2 / WARPS_C)// 16 tokens per warp
#define ESPLIT 4               // e-dimension split in kernel B
#define VBATCH 4               // docs per block in kernel B

// Scratch (static device globals — no allocation)
__device__ float        g_hpart[Bsz * NC1 * Dm];   // partial sums for h
__device__ float        g_vpart[ESPLIT][Bsz * Dm]; // e-partial dots of v = W_b @ h
__device__ float        g_ctf[Bsz * Dm];           // atomically accumulated ct numerator
__device__ float        g_df[Bsz];                 // atomically accumulated denom
__device__ unsigned int g_cnt[Bsz];                // fan-in counter per doc

// ---------------------------------------------------------------------------
// Kernel A: partial sums of embedding rows -> g_hpart[b, chunk, :]
// grid (Bsz, NC1), 512 threads = 16 warps. (R5 configuration — DRAM 59%.)
// ---------------------------------------------------------------------------
__global__ __launch_bounds__(512) void k_hpart(const int* __restrict__ tokens,
                                               const float* __restrict__ emb) {
    const int b = blockIdx.x, c = blockIdx.y;
    const int q  = threadIdx.x >> 7;
    const int t4 = threadIdx.x & 127;

    if (c == 0) {                       // zero accumulators for this replay
        g_ctf[b * Dm + threadIdx.x] = 0.0f;
        if (threadIdx.x == 0) { g_df[b] = 0.0f; g_cnt[b] = 0u; }
    }

    __shared__ int s_tok[TOK1];
    if (threadIdx.x < TOK1)
        s_tok[threadIdx.x] = tokens[b * Lseq + c * TOK1 + threadIdx.x] + 1;
    __syncthreads();

    float4 acc = make_float4(0.f, 0.f, 0.f, 0.f);
#pragma unroll 8
    for (int l = q; l < TOK1; l += QSPLIT) {
        int row = s_tok[l];
        float4 e = __ldg((const float4*)(emb) + row * (Dm / 4) + t4);
        acc.x += e.x; acc.y += e.y; acc.z += e.z; acc.w += e.w;
    }

    __shared__ float4 s_red[QSPLIT][128];
    s_red[q][t4] = acc;
    __syncthreads();

    if (q == 0) {
#pragma unroll
        for (int j = 1; j < QSPLIT; ++j) {
            float4 r = s_red[j][t4];
            acc.x += r.x; acc.y += r.y; acc.z += r.z; acc.w += r.w;
        }
        ((float4*)(g_hpart + (b * NC1 + c) * Dm))[t4] = acc;
    }
}

// ---------------------------------------------------------------------------
// Kernel B: e-split partial dots v[b,d] = sum_e W_b[d,e] * h[b,e]
// grid (Bsz/VBATCH, ESPLIT), 512 threads, thread = output row d.
// ---------------------------------------------------------------------------
__global__ __launch_bounds__(Dm) void k_v(const float* __restrict__ W) {
    const int bb = blockIdx.x * VBATCH;
    const int q  = blockIdx.y;              // e range [q*128, (q+1)*128)
    const int d  = threadIdx.x;

    __shared__ float s_h[VBATCH][128];
    {
        const int j  = threadIdx.x >> 7;    // doc within batch
        const int el = threadIdx.x & 127;   // local e
        float s = 0.0f;
#pragma unroll
        for (int c = 0; c < NC1; ++c)
            s += g_hpart[((bb + j) * NC1 + c) * Dm + q * 128 + el];
        s_h[j][el] = s * (1.0f / (float)Lseq);
    }
    __syncthreads();

    const float4* Wseg = (const float4*)(W + (long)d * Dm + q * 128);
    float a[VBATCH] = {0.f, 0.f, 0.f, 0.f};
#pragma unroll 8
    for (int e4 = 0; e4 < 32; ++e4) {
        float4 w = __ldg(Wseg + e4);
#pragma unroll
        for (int j = 0; j < VBATCH; ++j) {
            a[j] += w.x * s_h[j][e4 * 4 + 0] + w.y * s_h[j][e4 * 4 + 1]
                  + w.z * s_h[j][e4 * 4 + 2] + w.w * s_h[j][e4 * 4 + 3];
        }
    }
#pragma unroll
    for (int j = 0; j < VBATCH; ++j)
        g_vpart[q][(bb + j) * Dm + d] = a[j];
}

// ---------------------------------------------------------------------------
// Kernel C: fused score + exp + weighted accumulation + finalize.
// grid (Bsz, NC2), 256 threads = 8 warps; warp handles TOKW tokens, two per
// iteration, with a DEPTH-2 SOFTWARE PIPELINE: the next pair's 8 LDG.128 are
// issued before the current pair's shfl/exp/accum, hiding L2 latency.
// Lane owns 16 columns: cols 128*i + 4*lane + j.
// ---------------------------------------------------------------------------
__global__ __launch_bounds__(32 * WARPS_C) void k_attn(const int* __restrict__ tokens,
                                                       const float* __restrict__ emb,
                                                       float* __restrict__ out) {
    const int b = blockIdx.x, c = blockIdx.y;
    const int warp = threadIdx.x >> 5;
    const int lane = threadIdx.x & 31;

    __shared__ int   s_tok[TOK2];
    __shared__ float s_d[WARPS_C];
    __shared__ float s_ct[WARPS_C][Dm];   // 16 KB
    __shared__ bool  s_last;

    if (threadIdx.x < TOK2)
        s_tok[threadIdx.x] = tokens[b * Lseq + c * TOK2 + threadIdx.x] + 1;

    // this lane's 16 v values = sum of the 4 e-partials
    float4 vr[4];
#pragma unroll
    for (int i = 0; i < 4; ++i) {
        float4 s = make_float4(0.f, 0.f, 0.f, 0.f);
#pragma unroll
        for (int q = 0; q < ESPLIT; ++q) {
            float4 p = ((const float4*)(g_vpart[q] + b * Dm))[i * 32 + lane];
            s.x += p.x; s.y += p.y; s.z += p.z; s.w += p.w;
        }
        vr[i] = s;
    }
    __syncthreads();

    float dsum = 0.0f;
    float4 acc[4];
#pragma unroll
    for (int i = 0; i < 4; ++i) acc[i] = make_float4(0.f, 0.f, 0.f, 0.f);

    const int base = warp * TOKW;

    // pipeline prologue: load pair 0
    float4 ev0[4], ev1[4];
    {
        const float4* e0 = (const float4*)(emb) + s_tok[base + 0] * (Dm / 4);
        const float4* e1 = (const float4*)(emb) + s_tok[base + 1] * (Dm / 4);
#pragma unroll
        for (int i = 0; i < 4; ++i) ev0[i] = __ldg(e0 + i * 32 + lane);
#pragma unroll
        for (int i = 0; i < 4; ++i) ev1[i] = __ldg(e1 + i * 32 + lane);
    }

#pragma unroll
    for (int t = 0; t < TOKW; t += 2) {
        // issue next pair's loads first (wraps to 0 on last iter: harmless L1 hit)
        const int tn = (t + 2 < TOKW) ? t + 2 : 0;
        const float4* en0p = (const float4*)(emb) + s_tok[base + tn + 0] * (Dm / 4);
        const float4* en1p = (const float4*)(emb) + s_tok[base + tn + 1] * (Dm / 4);
        float4 en0[4], en1[4];
#pragma unroll
        for (int i = 0; i < 4; ++i) en0[i] = __ldg(en0p + i * 32 + lane);
#pragma unroll
        for (int i = 0; i < 4; ++i) en1[i] = __ldg(en1p + i * 32 + lane);

        // compute on current pair while next loads are in flight
        float s0 = 0.0f, s1 = 0.0f;
#pragma unroll
        for (int i = 0; i < 4; ++i) {
            s0 += ev0[i].x * vr[i].x + ev0[i].y * vr[i].y
                + ev0[i].z * vr[i].z + ev0[i].w * vr[i].w;
            s1 += ev1[i].x * vr[i].x + ev1[i].y * vr[i].y
                + ev1[i].z * vr[i].z + ev1[i].w * vr[i].w;
        }
#pragma unroll
        for (int off = 16; off > 0; off >>= 1) {
            s0 += __shfl_xor_sync(0xffffffffu, s0, off);
            s1 += __shfl_xor_sync(0xffffffffu, s1, off);
        }

        float p0 = __expf(s0);
        float p1 = __expf(s1);
        dsum += p0 + p1;
#pragma unroll
        for (int i = 0; i < 4; ++i) {
            acc[i].x += p0 * ev0[i].x + p1 * ev1[i].x;
            acc[i].y += p0 * ev0[i].y + p1 * ev1[i].y;
            acc[i].z += p0 * ev0[i].z + p1 * ev1[i].z;
            acc[i].w += p0 * ev0[i].w + p1 * ev1[i].w;
        }

        // rotate window (loop fully unrolled -> register renaming, no copies)
#pragma unroll
        for (int i = 0; i < 4; ++i) { ev0[i] = en0[i]; ev1[i] = en1[i]; }
    }

    if (lane == 0) s_d[warp] = dsum;
#pragma unroll
    for (int i = 0; i < 4; ++i) {
        int col = 128 * i + 4 * lane;
        s_ct[warp][col + 0] = acc[i].x;
        s_ct[warp][col + 1] = acc[i].y;
        s_ct[warp][col + 2] = acc[i].z;
        s_ct[warp][col + 3] = acc[i].w;
    }
    __syncthreads();

    // block reduce across warps, then RED into global accumulator
    for (int col = threadIdx.x; col < Dm; col += 32 * WARPS_C) {
        float cts = 0.0f;
#pragma unroll
        for (int w = 0; w < WARPS_C; ++w)
            cts += s_ct[w][col];
        atomicAdd(&g_ctf[b * Dm + col], cts);
    }
    if (threadIdx.x == 0) {
        float D = 0.0f;
#pragma unroll
        for (int w = 0; w < WARPS_C; ++w) D += s_d[w];
        atomicAdd(&g_df[b], D);
    }

    // fan-in: last block of this doc finalizes (threadFenceReduction pattern)
    __threadfence();
    __syncthreads();
    if (threadIdx.x == 0)
        s_last = (atomicAdd(&g_cnt[b], 1u) == NC2 - 1);
    __syncthreads();

    if (s_last) {
        const float inv = 1.0f / __ldcg(&g_df[b]);
        for (int col = threadIdx.x; col < Dm; col += 32 * WARPS_C)
            out[b * Dm + col] = __ldcg(&g_ctf[b * Dm + col]) * inv;
    }
}

// ---------------------------------------------------------------------------
extern "C" void kernel_launch(void* const* d_in, const int* in_sizes, int n_in,
                              void* d_out, int out_size) {
    const int*   tokens = (const int*)d_in[0];
    const float* emb    = (const float*)d_in[1];
    const float* W_b    = (const float*)d_in[2];
    float* out = (float*)d_out;

    k_hpart<<<dim3(Bsz, NC1), 512>>>(tokens, emb);
    k_v<<<dim3(Bsz / VBATCH, ESPLIT), Dm>>>(W_b);
    k_attn<<<dim3(Bsz, NC2), 32 * WARPS_C>>>(tokens, emb, out);
}

// round 10
// speedup vs baseline: 1.1217x; 1.1217x over previous
#include <cuda_runtime.h>

// Problem constants
#define Bsz    64
#define Lseq   2048
#define Dm     512
#define NC1    8               // chunks for mean pass (R5/R7-proven: A ~24us)
#define TOK1   (Lseq / NC1)    // 256 tokens per chunk
#define QSPLIT 4               // token-parallel groups inside a k_hpart block
#define NC2    16              // chunks for attention pass
#define TOK2   (Lseq / NC2)    // 128 tokens per chunk
#define WARPS_C 8              // warps per block in kernel C
#define TOKW   (TOK2 / WARPS_C)// 16 tokens per warp
#define ESPLIT 4               // e-dimension split in kernel B
#define VBATCH 4               // docs per block in kernel B

// Scratch (static device globals — no allocation)
__device__ float        g_hpart[Bsz * NC1 * Dm];   // partial sums for h
__device__ float        g_vpart[ESPLIT][Bsz * Dm]; // e-partial dots of v = W_b @ h
__device__ float        g_ctf[Bsz * Dm];           // atomically accumulated ct numerator
__device__ float        g_df[Bsz];                 // atomically accumulated denom
__device__ unsigned int g_cnt[Bsz];                // fan-in counter per doc

// ---------------------------------------------------------------------------
// Kernel A: partial sums of embedding rows -> g_hpart[b, chunk, :]
// grid (Bsz, NC1), 512 threads = 16 warps. (R5 configuration — DRAM ~58%.)
// ---------------------------------------------------------------------------
__global__ __launch_bounds__(512) void k_hpart(const int* __restrict__ tokens,
                                               const float* __restrict__ emb) {
    const int b = blockIdx.x, c = blockIdx.y;
    const int q  = threadIdx.x >> 7;
    const int t4 = threadIdx.x & 127;

    if (c == 0) {                       // zero accumulators for this replay
        g_ctf[b * Dm + threadIdx.x] = 0.0f;
        if (threadIdx.x == 0) { g_df[b] = 0.0f; g_cnt[b] = 0u; }
    }

    __shared__ int s_tok[TOK1];
    if (threadIdx.x < TOK1)
        s_tok[threadIdx.x] = tokens[b * Lseq + c * TOK1 + threadIdx.x] + 1;
    __syncthreads();

    float4 acc = make_float4(0.f, 0.f, 0.f, 0.f);
#pragma unroll 8
    for (int l = q; l < TOK1; l += QSPLIT) {
        int row = s_tok[l];
        float4 e = __ldg((const float4*)(emb) + row * (Dm / 4) + t4);
        acc.x += e.x; acc.y += e.y; acc.z += e.z; acc.w += e.w;
    }

    __shared__ float4 s_red[QSPLIT][128];
    s_red[q][t4] = acc;
    __syncthreads();

    if (q == 0) {
#pragma unroll
        for (int j = 1; j < QSPLIT; ++j) {
            float4 r = s_red[j][t4];
            acc.x += r.x; acc.y += r.y; acc.z += r.z; acc.w += r.w;
        }
        ((float4*)(g_hpart + (b * NC1 + c) * Dm))[t4] = acc;
    }
}

// ---------------------------------------------------------------------------
// Kernel B: e-split partial dots v[b,d] = sum_e W_b[d,e] * h[b,e]
// grid (Bsz/VBATCH, ESPLIT), 512 threads, thread = output row d.
// ---------------------------------------------------------------------------
__global__ __launch_bounds__(Dm) void k_v(const float* __restrict__ W) {
    const int bb = blockIdx.x * VBATCH;
    const int q  = blockIdx.y;              // e range [q*128, (q+1)*128)
    const int d  = threadIdx.x;

    __shared__ float s_h[VBATCH][128];
    {
        const int j  = threadIdx.x >> 7;    // doc within batch
        const int el = threadIdx.x & 127;   // local e
        float s = 0.0f;
#pragma unroll
        for (int c = 0; c < NC1; ++c)
            s += g_hpart[((bb + j) * NC1 + c) * Dm + q * 128 + el];
        s_h[j][el] = s * (1.0f / (float)Lseq);
    }
    __syncthreads();

    const float4* Wseg = (const float4*)(W + (long)d * Dm + q * 128);
    float a[VBATCH] = {0.f, 0.f, 0.f, 0.f};
#pragma unroll 8
    for (int e4 = 0; e4 < 32; ++e4) {
        float4 w = __ldg(Wseg + e4);
#pragma unroll
        for (int j = 0; j < VBATCH; ++j) {
            a[j] += w.x * s_h[j][e4 * 4 + 0] + w.y * s_h[j][e4 * 4 + 1]
                  + w.z * s_h[j][e4 * 4 + 2] + w.w * s_h[j][e4 * 4 + 3];
        }
    }
#pragma unroll
    for (int j = 0; j < VBATCH; ++j)
        g_vpart[q][(bb + j) * Dm + d] = a[j];
}

// ---------------------------------------------------------------------------
// Kernel C: fused score + exp + weighted accumulation + finalize.
// grid (Bsz, NC2), 256 threads = 8 warps; warp handles TOKW tokens, TWO per
// iteration (R6-proven interleave: 8 LDG in flight, 2 shfl trees, 2 MUFUs —
// NO deeper pipelining: depth>2 spills, confirmed R2 + R7).
// Lane owns 16 columns: cols 128*i + 4*lane + j.
// ---------------------------------------------------------------------------
__global__ __launch_bounds__(32 * WARPS_C) void k_attn(const int* __restrict__ tokens,
                                                       const float* __restrict__ emb,
                                                       float* __restrict__ out) {
    const int b = blockIdx.x, c = blockIdx.y;
    const int warp = threadIdx.x >> 5;
    const int lane = threadIdx.x & 31;

    __shared__ int   s_tok[TOK2];
    __shared__ float s_d[WARPS_C];
    __shared__ float s_ct[WARPS_C][Dm];   // 16 KB
    __shared__ bool  s_last;

    if (threadIdx.x < TOK2)
        s_tok[threadIdx.x] = tokens[b * Lseq + c * TOK2 + threadIdx.x] + 1;

    // this lane's 16 v values = sum of the 4 e-partials
    float4 vr[4];
#pragma unroll
    for (int i = 0; i < 4; ++i) {
        float4 s = make_float4(0.f, 0.f, 0.f, 0.f);
#pragma unroll
        for (int q = 0; q < ESPLIT; ++q) {
            float4 p = ((const float4*)(g_vpart[q] + b * Dm))[i * 32 + lane];
            s.x += p.x; s.y += p.y; s.z += p.z; s.w += p.w;
        }
        vr[i] = s;
    }
    __syncthreads();

    float dsum = 0.0f;
    float4 acc[4];
#pragma unroll
    for (int i = 0; i < 4; ++i) acc[i] = make_float4(0.f, 0.f, 0.f, 0.f);

    for (int t = 0; t < TOKW; t += 2) {
        int r0 = s_tok[warp * TOKW + t];
        int r1 = s_tok[warp * TOKW + t + 1];
        const float4* e0 = (const float4*)(emb) + r0 * (Dm / 4);
        const float4* e1 = (const float4*)(emb) + r1 * (Dm / 4);
        float4 ev0[4], ev1[4];
#pragma unroll
        for (int i = 0; i < 4; ++i) ev0[i] = __ldg(e0 + i * 32 + lane);
#pragma unroll
        for (int i = 0; i < 4; ++i) ev1[i] = __ldg(e1 + i * 32 + lane);

        float s0 = 0.0f, s1 = 0.0f;
#pragma unroll
        for (int i = 0; i < 4; ++i) {
            s0 += ev0[i].x * vr[i].x + ev0[i].y * vr[i].y
                + ev0[i].z * vr[i].z + ev0[i].w * vr[i].w;
            s1 += ev1[i].x * vr[i].x + ev1[i].y * vr[i].y
                + ev1[i].z * vr[i].z + ev1[i].w * vr[i].w;
        }
#pragma unroll
        for (int off = 16; off > 0; off >>= 1) {
            s0 += __shfl_xor_sync(0xffffffffu, s0, off);
            s1 += __shfl_xor_sync(0xffffffffu, s1, off);
        }

        float p0 = __expf(s0);
        float p1 = __expf(s1);
        dsum += p0 + p1;
#pragma unroll
        for (int i = 0; i < 4; ++i) {
            acc[i].x += p0 * ev0[i].x + p1 * ev1[i].x;
            acc[i].y += p0 * ev0[i].y + p1 * ev1[i].y;
            acc[i].z += p0 * ev0[i].z + p1 * ev1[i].z;
            acc[i].w += p0 * ev0[i].w + p1 * ev1[i].w;
        }
    }

    if (lane == 0) s_d[warp] = dsum;
#pragma unroll
    for (int i = 0; i < 4; ++i) {
        int col = 128 * i + 4 * lane;
        s_ct[warp][col + 0] = acc[i].x;
        s_ct[warp][col + 1] = acc[i].y;
        s_ct[warp][col + 2] = acc[i].z;
        s_ct[warp][col + 3] = acc[i].w;
    }
    __syncthreads();

    // block reduce across warps, then RED into global accumulator
    for (int col = threadIdx.x; col < Dm; col += 32 * WARPS_C) {
        float cts = 0.0f;
#pragma unroll
        for (int w = 0; w < WARPS_C; ++w)
            cts += s_ct[w][col];
        atomicAdd(&g_ctf[b * Dm + col], cts);
    }
    if (threadIdx.x == 0) {
        float D = 0.0f;
#pragma unroll
        for (int w = 0; w < WARPS_C; ++w) D += s_d[w];
        atomicAdd(&g_df[b], D);
    }

    // fan-in: last block of this doc finalizes (threadFenceReduction pattern)
    __threadfence();
    __syncthreads();
    if (threadIdx.x == 0)
        s_last = (atomicAdd(&g_cnt[b], 1u) == NC2 - 1);
    __syncthreads();

    if (s_last) {
        const float inv = 1.0f / __ldcg(&g_df[b]);
        for (int col = threadIdx.x; col < Dm; col += 32 * WARPS_C)
            out[b * Dm + col] = __ldcg(&g_ctf[b * Dm + col]) * inv;
    }
}

// ---------------------------------------------------------------------------
extern "C" void kernel_launch(void* const* d_in, const int* in_sizes, int n_in,
                              void* d_out, int out_size) {
    const int*   tokens = (const int*)d_in[0];
    const float* emb    = (const float*)d_in[1];
    const float* W_b    = (const float*)d_in[2];
    float* out = (float*)d_out;

    k_hpart<<<dim3(Bsz, NC1), 512>>>(tokens, emb);
    k_v<<<dim3(Bsz / VBATCH, ESPLIT), Dm>>>(W_b);
    k_attn<<<dim3(Bsz, NC2), 32 * WARPS_C>>>(tokens, emb, out);
}